// round 13
// baseline (speedup 1.0000x reference)
#include <cuda_runtime.h>
#include <cuda_bf16.h>
#include <cstdint>

// Problem constants
constexpr int B  = 32;
constexpr int T  = 4096;
constexpr int D  = 1024;
constexpr int H  = 8;
constexpr int HD = 128;
constexpr int P  = 1024;

// Device scratch (allocation-free rule: __device__ globals)
__device__ float    g_q[B * P];                   // relu(dec @ phi_w^T + phi_b)
__device__ float    g_energy[(size_t)B * H * T];  // energy, then score in-place
__device__ uint32_t g_whi[P * D / 2];             // psi_w split: bf16 hi pairs
__device__ uint32_t g_wlo[P * D / 2];             // psi_w split: bf16 lo pairs
__device__ uint32_t g_xhi[(size_t)B * T * D / 2]; // listener split: hi pairs
__device__ uint32_t g_xlo[(size_t)B * T * D / 2]; // listener split: lo pairs

// ---------------------------------------------------------------------------
// k2 config: tile M=128 (t rows) x N=128 (one head), K chunk 32, 512 threads,
// 16 warps in 4x4 grid (warp tile 32x32 -> 32 acc regs/thread, no spills).
// 3-stage cp.async pipeline; ALL operands pre-split bf16 in gmem.
// Smem rows padded to 80B (32 bf16 + 8 pad) -> conflict-free ldmatrix.
// ---------------------------------------------------------------------------
constexpr int KC   = 32;
constexpr int NK   = D / KC;        // 32 chunks
constexpr int NS   = 3;             // pipeline stages
constexpr int SROW = 80;            // bytes per smem row
constexpr int STG  = 128 * SROW;    // 10240 bytes per stage per half
// byte offsets in dynamic smem
constexpr int SM_XH = 0;
constexpr int SM_XL = SM_XH + NS * STG;   // 30720
constexpr int SM_WH = SM_XL + NS * STG;   // 61440
constexpr int SM_WL = SM_WH + NS * STG;   // 92160
constexpr int SM_Q  = SM_WL + NS * STG;   // 122880 (128 f)
constexpr int SM_BI = SM_Q + 512;         // 123392 (128 f)
constexpr int SM_E  = SM_BI + 512;        // 123904 (128 f)
constexpr int SM_TOTAL = SM_E + 512;      // 124416

// ---------------------------------------------------------------------------
// helpers
// ---------------------------------------------------------------------------
__device__ __forceinline__ uint32_t smem_u32(const void* p) {
    uint32_t a;
    asm("{ .reg .u64 t; cvta.to.shared.u64 t, %1; cvt.u32.u64 %0, t; }"
        : "=r"(a) : "l"(p));
    return a;
}

// Split two fp32 into packed bf16 hi pair + bf16 lo pair (x = hi + lo)
__device__ __forceinline__ void split2(float f0, float f1,
                                       uint32_t& hi, uint32_t& lo) {
    asm("cvt.rn.bf16x2.f32 %0, %1, %2;" : "=r"(hi) : "f"(f1), "f"(f0));
    const float h0 = __uint_as_float(hi << 16);
    const float h1 = __uint_as_float(hi & 0xffff0000u);
    const float l0 = f0 - h0;
    const float l1 = f1 - h1;
    asm("cvt.rn.bf16x2.f32 %0, %1, %2;" : "=r"(lo) : "f"(l1), "f"(l0));
}

__device__ __forceinline__ void cp_async16(uint32_t dst, const void* src) {
    asm volatile("cp.async.cg.shared.global [%0], [%1], 16;"
                 :: "r"(dst), "l"(src) : "memory");
}
__device__ __forceinline__ void cp_commit() {
    asm volatile("cp.async.commit_group;" ::: "memory");
}
__device__ __forceinline__ void cp_wait1() {
    asm volatile("cp.async.wait_group 1;" ::: "memory");
}

__device__ __forceinline__ void ldsm4(uint32_t* r, uint32_t addr) {
    asm volatile("ldmatrix.sync.aligned.m8n8.x4.shared.b16 {%0,%1,%2,%3}, [%4];"
                 : "=r"(r[0]), "=r"(r[1]), "=r"(r[2]), "=r"(r[3]) : "r"(addr));
}

__device__ __forceinline__ void mma16816(float* c, const uint32_t* a,
                                         const uint32_t* b) {
    asm volatile(
        "mma.sync.aligned.m16n8k16.row.col.f32.bf16.bf16.f32 "
        "{%0,%1,%2,%3}, {%4,%5,%6,%7}, {%8,%9}, {%0,%1,%2,%3};\n"
        : "+f"(c[0]), "+f"(c[1]), "+f"(c[2]), "+f"(c[3])
        : "r"(a[0]), "r"(a[1]), "r"(a[2]), "r"(a[3]), "r"(b[0]), "r"(b[1]));
}

// ---------------------------------------------------------------------------
// Kernel 0a: split psi_w into bf16 hi/lo pair arrays (row-major [P][D])
// ---------------------------------------------------------------------------
__global__ __launch_bounds__(256) void k0_wsplit(const float* __restrict__ psi_w)
{
    const int i = blockIdx.x * 256 + threadIdx.x;   // over P*D/2
    const float2 v = reinterpret_cast<const float2*>(psi_w)[i];
    uint32_t hi, lo;
    split2(v.x, v.y, hi, lo);
    g_whi[i] = hi;
    g_wlo[i] = lo;
}

// ---------------------------------------------------------------------------
// Kernel 0b: split listener_feature into bf16 hi/lo pair arrays
// ---------------------------------------------------------------------------
__global__ __launch_bounds__(256) void k0_xsplit(const float* __restrict__ lis)
{
    const size_t i = (size_t)blockIdx.x * 256 + threadIdx.x;  // over B*T*D/4
    const float4 v = reinterpret_cast<const float4*>(lis)[i];
    uint32_t h0, l0, h1, l1;
    split2(v.x, v.y, h0, l0);
    split2(v.z, v.w, h1, l1);
    reinterpret_cast<uint2*>(g_xhi)[i] = make_uint2(h0, h1);
    reinterpret_cast<uint2*>(g_xlo)[i] = make_uint2(l0, l1);
}

// ---------------------------------------------------------------------------
// Kernel 1: g_q[b, p] = relu(dec[b,:] . phi_w[p,:] + phi_b[p])
// ---------------------------------------------------------------------------
__global__ __launch_bounds__(256) void k1_q(
    const float* __restrict__ dec,
    const float* __restrict__ phi_w,
    const float* __restrict__ phi_b)
{
    const int b  = blockIdx.x;
    const int p0 = blockIdx.y * 128;
    __shared__ float sd[D];
    for (int i = threadIdx.x; i < D; i += 256) sd[i] = dec[b * D + i];
    __syncthreads();

    const int warp = threadIdx.x >> 5, lane = threadIdx.x & 31;
    for (int pi = warp; pi < 128; pi += 8) {
        const int p = p0 + pi;
        const float* wrow = phi_w + (size_t)p * D;
        float acc = 0.f;
        #pragma unroll 4
        for (int k = lane; k < D; k += 32) acc += sd[k] * wrow[k];
        #pragma unroll
        for (int o = 16; o; o >>= 1) acc += __shfl_xor_sync(0xffffffffu, acc, o);
        if (lane == 0) g_q[b * P + p] = fmaxf(acc + phi_b[p], 0.f);
    }
}

// ---------------------------------------------------------------------------
// Kernel 2: fused GEMM + energy via HMMA (mma.sync bf16, 3-term split).
// Grid (H, T/128, B) — head fastest so 8 CTAs share each X tile in L2.
// Pure cp.async producer (pre-split operands), 3-stage pipeline.
// Epilogue: e[t] = sum_n q[n]*relu(C[t][n]+bias[n]) -> g_energy.
// ---------------------------------------------------------------------------
__global__ __launch_bounds__(512, 1) void k2_energy(
    const float* __restrict__ psi_b)
{
    extern __shared__ char smraw[];
    const uint32_t sb = smem_u32(smraw);

    const int tid  = threadIdx.x;
    const int warp = tid >> 5, lane = tid & 31;
    const int h  = blockIdx.x;
    const int t0 = blockIdx.y * 128;
    const int b  = blockIdx.z;

    float* Sq = (float*)(smraw + SM_Q);
    float* Sb = (float*)(smraw + SM_BI);
    float* Se = (float*)(smraw + SM_E);
    if (tid < 128) {
        Sq[tid] = g_q[b * P + h * HD + tid];
        Sb[tid] = psi_b[h * HD + tid];
        Se[tid] = 0.f;
    }

    // per-thread cp.async mapping: 512 granules (16B) per array per chunk
    const int row = tid >> 2, g4 = tid & 3;
    const uint32_t* xh_src = g_xhi + ((size_t)b * T + t0 + row) * (D / 2) + g4 * 4;
    const uint32_t* xl_src = g_xlo + ((size_t)b * T + t0 + row) * (D / 2) + g4 * 4;
    const uint32_t* wh_src = g_whi + (size_t)(h * HD + row) * (D / 2) + g4 * 4;
    const uint32_t* wl_src = g_wlo + (size_t)(h * HD + row) * (D / 2) + g4 * 4;
    const uint32_t dof = (uint32_t)(row * SROW + g4 * 16);

    // ldmatrix lane offsets (within a 16x16 tile, row stride SROW)
    const int l7 = lane & 7;
    const uint32_t aoff = (uint32_t)((l7 + 8 * ((lane >> 3) & 1)) * SROW +
                                     16 * (lane >> 4));
    const uint32_t boff = (uint32_t)((l7 + 8 * (lane >> 4)) * SROW +
                                     16 * ((lane >> 3) & 1));

    const int wm = warp >> 2, wn = warp & 3;
    const int m0 = wm * 32, n0 = wn * 32;

    float acc[2][4][4];
    #pragma unroll
    for (int mi = 0; mi < 2; mi++)
        #pragma unroll
        for (int ni = 0; ni < 4; ni++)
            #pragma unroll
            for (int k = 0; k < 4; k++) acc[mi][ni][k] = 0.f;

    // prologue: stages 0,1 (chunks 0,1), one commit group each
    #pragma unroll
    for (int kc = 0; kc < 2; kc++) {
        const uint32_t so = (uint32_t)(kc * STG);
        cp_async16(sb + SM_XH + so + dof, xh_src + kc * (KC / 2));
        cp_async16(sb + SM_XL + so + dof, xl_src + kc * (KC / 2));
        cp_async16(sb + SM_WH + so + dof, wh_src + kc * (KC / 2));
        cp_async16(sb + SM_WL + so + dof, wl_src + kc * (KC / 2));
        cp_commit();
    }

    int st = 0, pf = 2 % NS;
    for (int kc = 0; kc < NK; kc++) {
        cp_wait1();          // chunk kc's group retired
        __syncthreads();     // data visible; stage pf's old readers done

        const int kn = kc + 2;
        if (kn < NK) {
            const uint32_t so = (uint32_t)(pf * STG);
            cp_async16(sb + SM_XH + so + dof, xh_src + kn * (KC / 2));
            cp_async16(sb + SM_XL + so + dof, xl_src + kn * (KC / 2));
            cp_async16(sb + SM_WH + so + dof, wh_src + kn * (KC / 2));
            cp_async16(sb + SM_WL + so + dof, wl_src + kn * (KC / 2));
        }
        cp_commit();

        const uint32_t xh = sb + SM_XH + st * STG;
        const uint32_t xl = sb + SM_XL + st * STG;
        const uint32_t wh = sb + SM_WH + st * STG;
        const uint32_t wl = sb + SM_WL + st * STG;

        #pragma unroll
        for (int ks = 0; ks < 2; ks++) {
            const uint32_t kofs = (uint32_t)(ks * 32);   // 16 bf16 = 32 bytes
            uint32_t ahi[2][4], alo[2][4];
            #pragma unroll
            for (int mi = 0; mi < 2; mi++) {
                const uint32_t rb = (uint32_t)((m0 + 16 * mi) * SROW) + kofs;
                ldsm4(ahi[mi], xh + rb + aoff);
                ldsm4(alo[mi], xl + rb + aoff);
            }
            #pragma unroll
            for (int np = 0; np < 2; np++) {
                const uint32_t rb = (uint32_t)((n0 + 16 * np) * SROW) + kofs;
                uint32_t bh[4], bl[4];
                ldsm4(bh, wh + rb + boff);
                ldsm4(bl, wl + rb + boff);
                #pragma unroll
                for (int mi = 0; mi < 2; mi++) {
                    mma16816(acc[mi][2 * np],     ahi[mi], bh);       // hi*hi
                    mma16816(acc[mi][2 * np + 1], ahi[mi], bh + 2);
                    mma16816(acc[mi][2 * np],     alo[mi], bh);       // lo*hi
                    mma16816(acc[mi][2 * np + 1], alo[mi], bh + 2);
                    mma16816(acc[mi][2 * np],     ahi[mi], bl);       // hi*lo
                    mma16816(acc[mi][2 * np + 1], ahi[mi], bl + 2);
                }
            }
        }
        st = (st + 1 == NS) ? 0 : st + 1;
        pf = (pf + 1 == NS) ? 0 : pf + 1;
    }

    // Epilogue: e[row] += q[col]*relu(acc+bias[col]); reduce over quad lanes
    const int g = lane >> 2, l = lane & 3;
    float ep[2][2] = {{0.f, 0.f}, {0.f, 0.f}};
    #pragma unroll
    for (int mi = 0; mi < 2; mi++) {
        #pragma unroll
        for (int ni = 0; ni < 4; ni++) {
            const int c0 = n0 + ni * 8 + 2 * l;
            const float q0 = Sq[c0],  q1 = Sq[c0 + 1];
            const float b0 = Sb[c0],  b1 = Sb[c0 + 1];
            ep[mi][0] += q0 * fmaxf(acc[mi][ni][0] + b0, 0.f)
                       + q1 * fmaxf(acc[mi][ni][1] + b1, 0.f);
            ep[mi][1] += q0 * fmaxf(acc[mi][ni][2] + b0, 0.f)
                       + q1 * fmaxf(acc[mi][ni][3] + b1, 0.f);
        }
    }
    #pragma unroll
    for (int o = 1; o <= 2; o <<= 1) {
        #pragma unroll
        for (int mi = 0; mi < 2; mi++) {
            ep[mi][0] += __shfl_xor_sync(0xffffffffu, ep[mi][0], o);
            ep[mi][1] += __shfl_xor_sync(0xffffffffu, ep[mi][1], o);
        }
    }
    if (l == 0) {
        #pragma unroll
        for (int mi = 0; mi < 2; mi++) {
            atomicAdd(&Se[m0 + 16 * mi + g],     ep[mi][0]);
            atomicAdd(&Se[m0 + 16 * mi + 8 + g], ep[mi][1]);
        }
    }
    __syncthreads();
    if (tid < 128)
        g_energy[((size_t)b * H + h) * T + t0 + tid] = Se[tid];
}

// ---------------------------------------------------------------------------
// Kernel 3: softmax over T per (b,h) row, in-place in g_energy.
// Writes score of the LAST head to out_score[b, t].
// ---------------------------------------------------------------------------
__global__ __launch_bounds__(256) void k3_softmax(float* __restrict__ out_score)
{
    const int row = blockIdx.x;          // b*H + h
    const int h = row & 7, b = row >> 3;
    float* e = g_energy + (size_t)row * T;
    const int tid = threadIdx.x;
    const int warp = tid >> 5, lane = tid & 31;

    float v[16];
    float m = -1e30f;
    #pragma unroll
    for (int i = 0; i < 16; i++) { v[i] = e[tid + i * 256]; m = fmaxf(m, v[i]); }
    #pragma unroll
    for (int o = 16; o; o >>= 1) m = fmaxf(m, __shfl_xor_sync(0xffffffffu, m, o));
    __shared__ float red[8];
    if (lane == 0) red[warp] = m;
    __syncthreads();
    m = red[0];
    #pragma unroll
    for (int w = 1; w < 8; w++) m = fmaxf(m, red[w]);

    float s = 0.f;
    #pragma unroll
    for (int i = 0; i < 16; i++) { v[i] = expf(v[i] - m); s += v[i]; }
    #pragma unroll
    for (int o = 16; o; o >>= 1) s += __shfl_xor_sync(0xffffffffu, s, o);
    __shared__ float red2[8];
    if (lane == 0) red2[warp] = s;
    __syncthreads();
    s = 0.f;
    #pragma unroll
    for (int w = 0; w < 8; w++) s += red2[w];

    const float inv = 1.f / s;
    #pragma unroll
    for (int i = 0; i < 16; i++) {
        const float sc = v[i] * inv;
        e[tid + i * 256] = sc;
        if (h == H - 1) out_score[(size_t)b * T + tid + i * 256] = sc;
    }
}

// ---------------------------------------------------------------------------
// Kernel 4: context[b, h*128+d] = sum_t score[b,h,t] * lis[b,t,h*128+d]
// ---------------------------------------------------------------------------
__global__ __launch_bounds__(256) void k4_context(
    const float* __restrict__ lis, float* __restrict__ ctx)
{
    const int bh = blockIdx.x;
    const int sidx = blockIdx.y;
    const int b = bh >> 3, h = bh & 7;
    const int tr = threadIdx.x >> 7;       // 0/1
    const int d  = threadIdx.x & 127;
    constexpr int TS = T / 8;              // 512 rows per block

    const float* lp = lis + (size_t)b * T * D + h * HD + d;
    const float* sp = g_energy + (size_t)bh * T;

    float acc = 0.f;
    const int tbeg = sidx * TS;
    #pragma unroll 4
    for (int t = tbeg + tr; t < tbeg + TS; t += 2)
        acc += sp[t] * lp[(size_t)t * D];

    __shared__ float sred[256];
    sred[threadIdx.x] = acc;
    __syncthreads();
    if (threadIdx.x < 128)
        atomicAdd(&ctx[b * D + h * HD + threadIdx.x],
                  sred[threadIdx.x] + sred[threadIdx.x + 128]);
}

// ---------------------------------------------------------------------------
// Host launch (graph-capturable: only async ops, no allocation)
// ---------------------------------------------------------------------------
extern "C" void kernel_launch(void* const* d_in, const int* in_sizes, int n_in,
                              void* d_out, int out_size)
{
    const float* dec   = (const float*)d_in[0];
    const float* lis   = (const float*)d_in[1];
    const float* phi_w = (const float*)d_in[2];
    const float* phi_b = (const float*)d_in[3];
    const float* psi_w = (const float*)d_in[4];
    const float* psi_b = (const float*)d_in[5];

    float* out = (float*)d_out;
    float* out_score = out;                       // [B, T]  (score of last head)
    float* out_ctx   = out + (size_t)B * T;       // [B, D]  (context)

    cudaFuncSetAttribute(k2_energy, cudaFuncAttributeMaxDynamicSharedMemorySize,
                         SM_TOTAL);

    cudaMemsetAsync(out_ctx, 0, (size_t)B * D * sizeof(float));
    k0_wsplit<<<P * D / 2 / 256, 256>>>(psi_w);
    k0_xsplit<<<(int)((size_t)B * T * D / 4 / 256), 256>>>(lis);
    k1_q<<<dim3(B, 8), 256>>>(dec, phi_w, phi_b);
    k2_energy<<<dim3(H, T / 128, B), 512, SM_TOTAL>>>(psi_b);
    k3_softmax<<<B * H, 256>>>(out_score);
    k4_context<<<dim3(B * H, 8), 256>>>(lis, out_ctx);
}